// round 1
// baseline (speedup 1.0000x reference)
#include <cuda_runtime.h>
#include <math.h>

#define V 33
#define V3 (V*V*V)          // 35937
#define BATCH 2
#define HW 2048
#define NPIX (HW*HW)

// ---------------- scratch (static device globals; no allocation) -------------
__device__ float  g_rs[BATCH*3*256*256];
__device__ float  g_a1[BATCH*16*128*128];
__device__ float  g_a2[BATCH*32*64*64];
__device__ float  g_a3[BATCH*64*32*32];
__device__ float  g_a4[BATCH*128*16*16];
__device__ float  g_a5[BATCH*128*8*8];
__device__ float  g_wts[BATCH*3];
__device__ float  g_vert[BATCH*3*V];
__device__ float4 g_lut[BATCH*V3];

// ---------------- stage 1: bilinear 2048 -> 256 (scale exactly 8) ------------
// src = 8*o + 3.5  => y0=8o+3, y1=8o+4, f=0.5 exactly.
__global__ void resize_k(const float* __restrict__ img) {
    int i = blockIdx.x * blockDim.x + threadIdx.x;
    if (i >= BATCH*3*256*256) return;
    int ox = i & 255;
    int oy = (i >> 8) & 255;
    int pc = i >> 16;                       // b*3 + c
    const float* p = img + (size_t)pc * NPIX;
    int iy = oy*8 + 3, ix = ox*8 + 3;
    float p00 = p[(size_t)iy*HW + ix];
    float p01 = p[(size_t)iy*HW + ix + 1];
    float p10 = p[(size_t)(iy+1)*HW + ix];
    float p11 = p[(size_t)(iy+1)*HW + ix + 1];
    float r0 = 0.5f*p00 + 0.5f*p10;         // y-interp first (matches ref order)
    float r1 = 0.5f*p01 + 0.5f*p11;
    g_rs[i] = 0.5f*r0 + 0.5f*r1;
}

// ---------------- direct conv 3x3 stride 2 pad 1, + bias + lrelu -------------
template<int CI, int CO, int HIN>
__global__ void conv_k(const float* __restrict__ in, const float* __restrict__ w,
                       const float* __restrict__ bias, float* __restrict__ out) {
    const int HO = HIN / 2;
    int i = blockIdx.x * blockDim.x + threadIdx.x;
    if (i >= BATCH*CO*HO*HO) return;
    int ox = i % HO;
    int t  = i / HO;
    int oy = t % HO;  t /= HO;
    int co = t % CO;
    int b  = t / CO;
    float acc = bias[co];
    const float* wb = w + (size_t)co*CI*9;
    const float* ib = in + (size_t)b*CI*HIN*HIN;
    int iy0 = oy*2 - 1, ix0 = ox*2 - 1;
    for (int ci = 0; ci < CI; ci++) {
        const float* ip = ib + (size_t)ci*HIN*HIN;
        const float* wp = wb + ci*9;
        #pragma unroll
        for (int ky = 0; ky < 3; ky++) {
            int iy = iy0 + ky;
            if ((unsigned)iy >= (unsigned)HIN) continue;
            #pragma unroll
            for (int kx = 0; kx < 3; kx++) {
                int ix = ix0 + kx;
                if ((unsigned)ix >= (unsigned)HIN) continue;
                acc += ip[iy*HIN + ix] * wp[ky*3 + kx];
            }
        }
    }
    out[i] = acc >= 0.f ? acc : 0.2f*acc;
}

// ---------------- instance norm, in place (block per (b,c)) ------------------
__global__ void inorm_k(float* __restrict__ x, const float* __restrict__ g,
                        const float* __restrict__ be, int C, int N) {
    int bc = blockIdx.x;
    int c  = bc % C;
    float* p = x + (size_t)bc * N;
    float s = 0.f, s2 = 0.f;
    for (int i = threadIdx.x; i < N; i += blockDim.x) { float v = p[i]; s += v; s2 += v*v; }
    __shared__ float sa[256], sb[256];
    sa[threadIdx.x] = s; sb[threadIdx.x] = s2;
    __syncthreads();
    for (int o = 128; o > 0; o >>= 1) {
        if (threadIdx.x < o) { sa[threadIdx.x] += sa[threadIdx.x+o]; sb[threadIdx.x] += sb[threadIdx.x+o]; }
        __syncthreads();
    }
    __shared__ float s_a, s_b;
    if (threadIdx.x == 0) {
        float m   = sa[0] / (float)N;
        float var = sb[0] / (float)N - m*m;
        float inv = rsqrtf(var + 1e-5f);
        float a   = inv * g[c];
        s_a = a;
        s_b = be[c] - m * a;
    }
    __syncthreads();
    float a = s_a, bt = s_b;
    for (int i = threadIdx.x; i < N; i += blockDim.x) p[i] = p[i]*a + bt;
}

// ---------------- pool 8x8 -> (2,2), FCs, softmax+cumsum ---------------------
__global__ void fc_k(const float* __restrict__ wgen_w, const float* __restrict__ wgen_b,
                     const float* __restrict__ ada_w,  const float* __restrict__ ada_b) {
    int b = blockIdx.x;
    int t = threadIdx.x;
    __shared__ float sx[512];
    __shared__ float slog[96];
    // pooled feature index = c*4 + i*2 + j  (4x4 mean blocks)
    {
        int c  = t >> 2;
        int ij = t & 3;
        int i0 = (ij >> 1) * 4;
        int j0 = (ij & 1) * 4;
        const float* p = g_a5 + (size_t)(b*128 + c) * 64;
        float s = 0.f;
        #pragma unroll
        for (int pp = 0; pp < 4; pp++)
            #pragma unroll
            for (int qq = 0; qq < 4; qq++)
                s += p[(i0+pp)*8 + j0+qq];
        sx[t] = s * (1.f/16.f);
    }
    __syncthreads();
    if (t < 96) {
        float d = ada_b[t];
        for (int m = 0; m < 512; m++) d += sx[m] * ada_w[m*96 + t];
        slog[t] = d;
    } else if (t < 99) {
        int n = t - 96;
        float d = wgen_b[n];
        for (int m = 0; m < 512; m++) d += sx[m] * wgen_w[m*3 + n];
        g_wts[b*3 + n] = d;
    }
    __syncthreads();
    if (t < 3) {
        float mx = -1e30f;
        for (int k = 0; k < 32; k++) mx = fmaxf(mx, slog[t*32 + k]);
        float e[32]; float sum = 0.f;
        for (int k = 0; k < 32; k++) { e[k] = expf(slog[t*32 + k] - mx); sum += e[k]; }
        float isum = 1.f / sum;
        float* vp = g_vert + (b*3 + t) * V;
        vp[0] = 0.f;
        float run = 0.f;
        for (int k = 0; k < 32; k++) { run += e[k]*isum; vp[k+1] = run; }
    }
}

// ---------------- build transposed LUT: float4 per (b, flat) -----------------
__global__ void lut_k(const float* __restrict__ basis_w) {
    int i = blockIdx.x * blockDim.x + threadIdx.x;
    if (i >= BATCH*V3) return;
    int b    = i / V3;
    int flat = i % V3;
    float w0 = g_wts[b*3+0], w1 = g_wts[b*3+1], w2 = g_wts[b*3+2];
    float4 o;
    o.x = w0*basis_w[0*3*V3 + 0*V3 + flat] + w1*basis_w[1*3*V3 + 0*V3 + flat] + w2*basis_w[2*3*V3 + 0*V3 + flat];
    o.y = w0*basis_w[0*3*V3 + 1*V3 + flat] + w1*basis_w[1*3*V3 + 1*V3 + flat] + w2*basis_w[2*3*V3 + 1*V3 + flat];
    o.z = w0*basis_w[0*3*V3 + 2*V3 + flat] + w1*basis_w[1*3*V3 + 2*V3 + flat] + w2*basis_w[2*3*V3 + 2*V3 + flat];
    o.w = 0.f;
    g_lut[i] = o;
}

// ---------------- the big one: trilinear LUT transform -----------------------
__device__ __forceinline__ void lut_lookup(const float* __restrict__ v, float q,
                                           int& idx, float& f) {
    q = fminf(fmaxf(q, 0.f), 1.f);
    int pos = 0;                      // v[0]==0 <= q always; result capped at 31
    #pragma unroll
    for (int s = 16; s >= 1; s >>= 1)
        if (v[pos + s] <= q) pos += s;
    idx = pos;
    float v0 = v[pos], v1 = v[pos+1];
    f = fminf(fmaxf((q - v0) / fmaxf(v1 - v0, 1e-10f), 0.f), 1.f);
}

__device__ __forceinline__ float3 apply_px(float r, float g, float bl,
        const float* __restrict__ vr, const float* __restrict__ vg,
        const float* __restrict__ vb, const float4* __restrict__ lb) {
    int ir, ig, ib;
    float fr, fg, fb;
    lut_lookup(vr, r,  ir, fr);
    lut_lookup(vg, g,  ig, fg);
    lut_lookup(vb, bl, ib, fb);
    int base = (ib*V + ig)*V + ir;
    float3 acc = make_float3(0.f, 0.f, 0.f);
    #pragma unroll
    for (int db = 0; db < 2; db++) {
        float wb_ = db ? fb : 1.f - fb;
        #pragma unroll
        for (int dg = 0; dg < 2; dg++) {
            float wg_ = wb_ * (dg ? fg : 1.f - fg);
            int off = base + db*V*V + dg*V;
            float4 t0 = __ldg(lb + off);
            float4 t1 = __ldg(lb + off + 1);
            float w0 = wg_ * (1.f - fr);
            float w1 = wg_ * fr;
            acc.x += w0*t0.x + w1*t1.x;
            acc.y += w0*t0.y + w1*t1.y;
            acc.z += w0*t0.z + w1*t1.z;
        }
    }
    return acc;
}

__global__ void trans_k(const float* __restrict__ img, float* __restrict__ out) {
    __shared__ float sv[BATCH*3*V];
    for (int i = threadIdx.x; i < BATCH*3*V; i += blockDim.x) sv[i] = g_vert[i];
    __syncthreads();
    const int QPI = NPIX / 4;
    int gid = blockIdx.x * blockDim.x + threadIdx.x;
    if (gid >= BATCH*QPI) return;
    int b = gid / QPI;
    int q = gid % QPI;
    const float4* rp = (const float4*)(img + (size_t)(b*3+0)*NPIX);
    const float4* gp = (const float4*)(img + (size_t)(b*3+1)*NPIX);
    const float4* bp = (const float4*)(img + (size_t)(b*3+2)*NPIX);
    float4 R = rp[q], G = gp[q], Bl = bp[q];
    const float* vr = sv + (b*3+0)*V;
    const float* vg = sv + (b*3+1)*V;
    const float* vb = sv + (b*3+2)*V;
    const float4* lb = g_lut + (size_t)b*V3;

    float3 o0 = apply_px(R.x, G.x, Bl.x, vr, vg, vb, lb);
    float3 o1 = apply_px(R.y, G.y, Bl.y, vr, vg, vb, lb);
    float3 o2 = apply_px(R.z, G.z, Bl.z, vr, vg, vb, lb);
    float3 o3 = apply_px(R.w, G.w, Bl.w, vr, vg, vb, lb);

    float4* orp = (float4*)(out + (size_t)(b*3+0)*NPIX);
    float4* ogp = (float4*)(out + (size_t)(b*3+1)*NPIX);
    float4* obp = (float4*)(out + (size_t)(b*3+2)*NPIX);
    orp[q] = make_float4(o0.x, o1.x, o2.x, o3.x);
    ogp[q] = make_float4(o0.y, o1.y, o2.y, o3.y);
    obp[q] = make_float4(o0.z, o1.z, o2.z, o3.z);
}

// ---------------- launch ------------------------------------------------------
extern "C" void kernel_launch(void* const* d_in, const int* in_sizes, int n_in,
                              void* d_out, int out_size) {
    const float* imgs   = (const float*)d_in[0];
    const float* w1 = (const float*)d_in[1];  const float* b1 = (const float*)d_in[2];
    const float* g1 = (const float*)d_in[3];  const float* be1 = (const float*)d_in[4];
    const float* w2 = (const float*)d_in[5];  const float* b2 = (const float*)d_in[6];
    const float* g2 = (const float*)d_in[7];  const float* be2 = (const float*)d_in[8];
    const float* w3 = (const float*)d_in[9];  const float* b3 = (const float*)d_in[10];
    const float* g3 = (const float*)d_in[11]; const float* be3 = (const float*)d_in[12];
    const float* w4 = (const float*)d_in[13]; const float* b4 = (const float*)d_in[14];
    const float* g4 = (const float*)d_in[15]; const float* be4 = (const float*)d_in[16];
    const float* w5 = (const float*)d_in[17]; const float* b5 = (const float*)d_in[18];
    const float* wgen_w = (const float*)d_in[19]; const float* wgen_b = (const float*)d_in[20];
    const float* basis_w = (const float*)d_in[21];
    const float* ada_w = (const float*)d_in[22]; const float* ada_b = (const float*)d_in[23];
    float* out = (float*)d_out;

    void *p_rs, *p_a1, *p_a2, *p_a3, *p_a4, *p_a5;
    cudaGetSymbolAddress(&p_rs, g_rs);
    cudaGetSymbolAddress(&p_a1, g_a1);
    cudaGetSymbolAddress(&p_a2, g_a2);
    cudaGetSymbolAddress(&p_a3, g_a3);
    cudaGetSymbolAddress(&p_a4, g_a4);
    cudaGetSymbolAddress(&p_a5, g_a5);

    const int T = 256;

    // stage 1: resize
    resize_k<<<(BATCH*3*256*256 + T-1)/T, T>>>(imgs);

    // stage 2: backbone
    conv_k<3,  16, 256><<<(BATCH*16*128*128 + T-1)/T, T>>>((const float*)p_rs, w1, b1, (float*)p_a1);
    inorm_k<<<BATCH*16,  T>>>((float*)p_a1, g1, be1, 16, 128*128);
    conv_k<16, 32, 128><<<(BATCH*32*64*64   + T-1)/T, T>>>((const float*)p_a1, w2, b2, (float*)p_a2);
    inorm_k<<<BATCH*32,  T>>>((float*)p_a2, g2, be2, 32, 64*64);
    conv_k<32, 64, 64 ><<<(BATCH*64*32*32   + T-1)/T, T>>>((const float*)p_a2, w3, b3, (float*)p_a3);
    inorm_k<<<BATCH*64,  T>>>((float*)p_a3, g3, be3, 64, 32*32);
    conv_k<64, 128, 32><<<(BATCH*128*16*16  + T-1)/T, T>>>((const float*)p_a3, w4, b4, (float*)p_a4);
    inorm_k<<<BATCH*128, T>>>((float*)p_a4, g4, be4, 128, 16*16);
    conv_k<128,128, 16><<<(BATCH*128*8*8    + T-1)/T, T>>>((const float*)p_a4, w5, b5, (float*)p_a5);

    // stage 3: pooled features -> weights, vertices; build transposed LUT
    fc_k<<<BATCH, 512>>>(wgen_w, wgen_b, ada_w, ada_b);
    lut_k<<<(BATCH*V3 + T-1)/T, T>>>(basis_w);

    // stage 4: full-res trilinear LUT transform
    trans_k<<<(BATCH*(NPIX/4) + T-1)/T, T>>>(imgs, out);
}

// round 2
// speedup vs baseline: 1.0630x; 1.0630x over previous
#include <cuda_runtime.h>
#include <cuda_fp16.h>
#include <math.h>

#define V 33
#define V3 (V*V*V)          // 35937
#define BATCH 2
#define HW 2048
#define NPIX (HW*HW)

// ---------------- scratch (static device globals; no allocation) -------------
__device__ float  g_rs[BATCH*3*256*256];
__device__ float  g_a1[BATCH*16*128*128];
__device__ float  g_a2[BATCH*32*64*64];
__device__ float  g_a3[BATCH*64*32*32];
__device__ float  g_a4[BATCH*128*16*16];
__device__ float  g_a5[BATCH*128*8*8];
__device__ float  g_wts[BATCH*3];
__device__ float  g_vert[BATCH*3*V];

// fp16 pair-packed LUT: entry i holds {r,g,b} of cells i and i+1 (16B aligned)
struct alignas(16) LutPair { __half2 rr, gg, bb, pad; };
__device__ LutPair g_lut16[BATCH*V3];

// ---------------- stage 1: bilinear 2048 -> 256 (scale exactly 8) ------------
__global__ void resize_k(const float* __restrict__ img) {
    int i = blockIdx.x * blockDim.x + threadIdx.x;
    if (i >= BATCH*3*256*256) return;
    int ox = i & 255;
    int oy = (i >> 8) & 255;
    int pc = i >> 16;                       // b*3 + c
    const float* p = img + (size_t)pc * NPIX;
    int iy = oy*8 + 3, ix = ox*8 + 3;
    float p00 = p[(size_t)iy*HW + ix];
    float p01 = p[(size_t)iy*HW + ix + 1];
    float p10 = p[(size_t)(iy+1)*HW + ix];
    float p11 = p[(size_t)(iy+1)*HW + ix + 1];
    float r0 = 0.5f*p00 + 0.5f*p10;
    float r1 = 0.5f*p01 + 0.5f*p11;
    g_rs[i] = 0.5f*r0 + 0.5f*r1;
}

// ---------------- direct conv 3x3 stride 2 pad 1, + bias + lrelu -------------
template<int CI, int CO, int HIN>
__global__ __launch_bounds__(256) void conv_k(const float* __restrict__ in,
                       const float* __restrict__ w,
                       const float* __restrict__ bias, float* __restrict__ out) {
    const int HO = HIN / 2;
    int i = blockIdx.x * blockDim.x + threadIdx.x;
    if (i >= BATCH*CO*HO*HO) return;
    int ox = i % HO;
    int t  = i / HO;
    int oy = t % HO;  t /= HO;
    int co = t % CO;
    int b  = t / CO;
    float acc = bias[co];
    const float* wb = w + (size_t)co*CI*9;
    const float* ib = in + (size_t)b*CI*HIN*HIN;
    int iy0 = oy*2 - 1, ix0 = ox*2 - 1;
    if (iy0 >= 0 && ix0 >= 0) {
        // interior fast path (iy0+2 <= HIN-1, ix0+2 <= HIN-1 always hold)
        const float* ip = ib + (size_t)iy0*HIN + ix0;
        const float* wp = wb;
        #pragma unroll 2
        for (int ci = 0; ci < CI; ci++) {
            acc += ip[0]      *wp[0] + ip[1]      *wp[1] + ip[2]      *wp[2];
            acc += ip[HIN]    *wp[3] + ip[HIN+1]  *wp[4] + ip[HIN+2]  *wp[5];
            acc += ip[2*HIN]  *wp[6] + ip[2*HIN+1]*wp[7] + ip[2*HIN+2]*wp[8];
            ip += HIN*HIN;
            wp += 9;
        }
    } else {
        for (int ci = 0; ci < CI; ci++) {
            const float* ip = ib + (size_t)ci*HIN*HIN;
            const float* wp = wb + ci*9;
            #pragma unroll
            for (int ky = 0; ky < 3; ky++) {
                int iy = iy0 + ky;
                if ((unsigned)iy >= (unsigned)HIN) continue;
                #pragma unroll
                for (int kx = 0; kx < 3; kx++) {
                    int ix = ix0 + kx;
                    if ((unsigned)ix >= (unsigned)HIN) continue;
                    acc += ip[iy*HIN + ix] * wp[ky*3 + kx];
                }
            }
        }
    }
    out[i] = acc >= 0.f ? acc : 0.2f*acc;
}

// ---------------- instance norm, in place (block per (b,c)) ------------------
__global__ void inorm_k(float* __restrict__ x, const float* __restrict__ g,
                        const float* __restrict__ be, int C, int N) {
    int bc = blockIdx.x;
    int c  = bc % C;
    float* p = x + (size_t)bc * N;
    float s = 0.f, s2 = 0.f;
    for (int i = threadIdx.x; i < N; i += blockDim.x) { float v = p[i]; s += v; s2 += v*v; }
    __shared__ float sa[256], sb[256];
    sa[threadIdx.x] = s; sb[threadIdx.x] = s2;
    __syncthreads();
    for (int o = 128; o > 0; o >>= 1) {
        if (threadIdx.x < o) { sa[threadIdx.x] += sa[threadIdx.x+o]; sb[threadIdx.x] += sb[threadIdx.x+o]; }
        __syncthreads();
    }
    __shared__ float s_a, s_b;
    if (threadIdx.x == 0) {
        float m   = sa[0] / (float)N;
        float var = sb[0] / (float)N - m*m;
        float inv = rsqrtf(var + 1e-5f);
        float a   = inv * g[c];
        s_a = a;
        s_b = be[c] - m * a;
    }
    __syncthreads();
    float a = s_a, bt = s_b;
    for (int i = threadIdx.x; i < N; i += blockDim.x) p[i] = p[i]*a + bt;
}

// ---------------- pool 8x8 -> (2,2), FCs, softmax+cumsum ---------------------
__global__ void fc_k(const float* __restrict__ wgen_w, const float* __restrict__ wgen_b,
                     const float* __restrict__ ada_w,  const float* __restrict__ ada_b) {
    int b = blockIdx.x;
    int t = threadIdx.x;
    __shared__ float sx[512];
    __shared__ float slog[96];
    {
        int c  = t >> 2;
        int ij = t & 3;
        int i0 = (ij >> 1) * 4;
        int j0 = (ij & 1) * 4;
        const float* p = g_a5 + (size_t)(b*128 + c) * 64;
        float s = 0.f;
        #pragma unroll
        for (int pp = 0; pp < 4; pp++)
            #pragma unroll
            for (int qq = 0; qq < 4; qq++)
                s += p[(i0+pp)*8 + j0+qq];
        sx[t] = s * (1.f/16.f);
    }
    __syncthreads();
    if (t < 96) {
        float d = ada_b[t];
        for (int m = 0; m < 512; m++) d += sx[m] * ada_w[m*96 + t];
        slog[t] = d;
    } else if (t < 99) {
        int n = t - 96;
        float d = wgen_b[n];
        for (int m = 0; m < 512; m++) d += sx[m] * wgen_w[m*3 + n];
        g_wts[b*3 + n] = d;
    }
    __syncthreads();
    if (t < 3) {
        float mx = -1e30f;
        for (int k = 0; k < 32; k++) mx = fmaxf(mx, slog[t*32 + k]);
        float e[32]; float sum = 0.f;
        for (int k = 0; k < 32; k++) { e[k] = expf(slog[t*32 + k] - mx); sum += e[k]; }
        float isum = 1.f / sum;
        float* vp = g_vert + (b*3 + t) * V;
        vp[0] = 0.f;
        float run = 0.f;
        for (int k = 0; k < 32; k++) { run += e[k]*isum; vp[k+1] = run; }
    }
}

// ---------------- build fp16 pair-packed LUT ---------------------------------
__global__ void lut_k(const float* __restrict__ basis_w) {
    int i = blockIdx.x * blockDim.x + threadIdx.x;
    if (i >= BATCH*V3) return;
    int b    = i / V3;
    int flat = i % V3;
    int flat2 = flat + 1 < V3 ? flat + 1 : V3 - 1;
    float w0 = g_wts[b*3+0], w1 = g_wts[b*3+1], w2 = g_wts[b*3+2];
    float r0 = w0*basis_w[0*3*V3 + 0*V3 + flat]  + w1*basis_w[1*3*V3 + 0*V3 + flat]  + w2*basis_w[2*3*V3 + 0*V3 + flat];
    float g0 = w0*basis_w[0*3*V3 + 1*V3 + flat]  + w1*basis_w[1*3*V3 + 1*V3 + flat]  + w2*basis_w[2*3*V3 + 1*V3 + flat];
    float b0 = w0*basis_w[0*3*V3 + 2*V3 + flat]  + w1*basis_w[1*3*V3 + 2*V3 + flat]  + w2*basis_w[2*3*V3 + 2*V3 + flat];
    float r1 = w0*basis_w[0*3*V3 + 0*V3 + flat2] + w1*basis_w[1*3*V3 + 0*V3 + flat2] + w2*basis_w[2*3*V3 + 0*V3 + flat2];
    float g1 = w0*basis_w[0*3*V3 + 1*V3 + flat2] + w1*basis_w[1*3*V3 + 1*V3 + flat2] + w2*basis_w[2*3*V3 + 1*V3 + flat2];
    float b1 = w0*basis_w[0*3*V3 + 2*V3 + flat2] + w1*basis_w[1*3*V3 + 2*V3 + flat2] + w2*basis_w[2*3*V3 + 2*V3 + flat2];
    LutPair o;
    o.rr = __floats2half2_rn(r0, r1);
    o.gg = __floats2half2_rn(g0, g1);
    o.bb = __floats2half2_rn(b0, b1);
    o.pad = __floats2half2_rn(0.f, 0.f);
    g_lut16[i] = o;
}

// ---------------- trilinear LUT transform ------------------------------------
__device__ __forceinline__ void lut_lookup(const float* __restrict__ v, float q,
                                           int& idx, float& f) {
    q = fminf(fmaxf(q, 0.f), 1.f);
    int pos = 0;
    #pragma unroll
    for (int s = 16; s >= 1; s >>= 1)
        if (v[pos + s] <= q) pos += s;
    idx = pos;
    float v0 = v[pos], v1 = v[pos+1];
    f = fminf(fmaxf((q - v0) / fmaxf(v1 - v0, 1e-10f), 0.f), 1.f);
}

__device__ __forceinline__ float3 apply_px(float r, float g, float bl,
        const float* __restrict__ vr, const float* __restrict__ vg,
        const float* __restrict__ vb, const float4* __restrict__ lb) {
    int ir, ig, ib;
    float fr, fg, fb;
    lut_lookup(vr, r,  ir, fr);
    lut_lookup(vg, g,  ig, fg);
    lut_lookup(vb, bl, ib, fb);
    int base = (ib*V + ig)*V + ir;
    float3 acc = make_float3(0.f, 0.f, 0.f);
    float omfr = 1.f - fr;
    #pragma unroll
    for (int db = 0; db < 2; db++) {
        float wb_ = db ? fb : 1.f - fb;
        #pragma unroll
        for (int dg = 0; dg < 2; dg++) {
            float wg_ = wb_ * (dg ? fg : 1.f - fg);
            int off = base + db*V*V + dg*V;
            float4 raw = __ldg(lb + off);
            float2 rv = __half22float2(*reinterpret_cast<const __half2*>(&raw.x));
            float2 gv = __half22float2(*reinterpret_cast<const __half2*>(&raw.y));
            float2 bv = __half22float2(*reinterpret_cast<const __half2*>(&raw.z));
            float w0 = wg_ * omfr;
            float w1 = wg_ * fr;
            acc.x += w0*rv.x + w1*rv.y;
            acc.y += w0*gv.x + w1*gv.y;
            acc.z += w0*bv.x + w1*bv.y;
        }
    }
    return acc;
}

__global__ __launch_bounds__(256) void trans_k(const float* __restrict__ img,
                                               float* __restrict__ out) {
    __shared__ float sv[BATCH*3*V];
    for (int i = threadIdx.x; i < BATCH*3*V; i += blockDim.x) sv[i] = g_vert[i];
    __syncthreads();
    const int QPI = NPIX / 4;
    int gid = blockIdx.x * blockDim.x + threadIdx.x;
    if (gid >= BATCH*QPI) return;
    int b = gid / QPI;
    int q = gid % QPI;
    const float4* rp = (const float4*)(img + (size_t)(b*3+0)*NPIX);
    const float4* gp = (const float4*)(img + (size_t)(b*3+1)*NPIX);
    const float4* bp = (const float4*)(img + (size_t)(b*3+2)*NPIX);
    float4 R = rp[q], G = gp[q], Bl = bp[q];
    const float* vr = sv + (b*3+0)*V;
    const float* vg = sv + (b*3+1)*V;
    const float* vb = sv + (b*3+2)*V;
    const float4* lb = reinterpret_cast<const float4*>(g_lut16) + (size_t)b*V3;

    float3 o0 = apply_px(R.x, G.x, Bl.x, vr, vg, vb, lb);
    float3 o1 = apply_px(R.y, G.y, Bl.y, vr, vg, vb, lb);
    float3 o2 = apply_px(R.z, G.z, Bl.z, vr, vg, vb, lb);
    float3 o3 = apply_px(R.w, G.w, Bl.w, vr, vg, vb, lb);

    float4* orp = (float4*)(out + (size_t)(b*3+0)*NPIX);
    float4* ogp = (float4*)(out + (size_t)(b*3+1)*NPIX);
    float4* obp = (float4*)(out + (size_t)(b*3+2)*NPIX);
    orp[q] = make_float4(o0.x, o1.x, o2.x, o3.x);
    ogp[q] = make_float4(o0.y, o1.y, o2.y, o3.y);
    obp[q] = make_float4(o0.z, o1.z, o2.z, o3.z);
}

// ---------------- launch ------------------------------------------------------
extern "C" void kernel_launch(void* const* d_in, const int* in_sizes, int n_in,
                              void* d_out, int out_size) {
    const float* imgs   = (const float*)d_in[0];
    const float* w1 = (const float*)d_in[1];  const float* b1 = (const float*)d_in[2];
    const float* g1 = (const float*)d_in[3];  const float* be1 = (const float*)d_in[4];
    const float* w2 = (const float*)d_in[5];  const float* b2 = (const float*)d_in[6];
    const float* g2 = (const float*)d_in[7];  const float* be2 = (const float*)d_in[8];
    const float* w3 = (const float*)d_in[9];  const float* b3 = (const float*)d_in[10];
    const float* g3 = (const float*)d_in[11]; const float* be3 = (const float*)d_in[12];
    const float* w4 = (const float*)d_in[13]; const float* b4 = (const float*)d_in[14];
    const float* g4 = (const float*)d_in[15]; const float* be4 = (const float*)d_in[16];
    const float* w5 = (const float*)d_in[17]; const float* b5 = (const float*)d_in[18];
    const float* wgen_w = (const float*)d_in[19]; const float* wgen_b = (const float*)d_in[20];
    const float* basis_w = (const float*)d_in[21];
    const float* ada_w = (const float*)d_in[22]; const float* ada_b = (const float*)d_in[23];
    float* out = (float*)d_out;

    void *p_rs, *p_a1, *p_a2, *p_a3, *p_a4, *p_a5;
    cudaGetSymbolAddress(&p_rs, g_rs);
    cudaGetSymbolAddress(&p_a1, g_a1);
    cudaGetSymbolAddress(&p_a2, g_a2);
    cudaGetSymbolAddress(&p_a3, g_a3);
    cudaGetSymbolAddress(&p_a4, g_a4);
    cudaGetSymbolAddress(&p_a5, g_a5);

    const int T = 256;

    resize_k<<<(BATCH*3*256*256 + T-1)/T, T>>>(imgs);

    conv_k<3,  16, 256><<<(BATCH*16*128*128 + T-1)/T, T>>>((const float*)p_rs, w1, b1, (float*)p_a1);
    inorm_k<<<BATCH*16,  T>>>((float*)p_a1, g1, be1, 16, 128*128);
    conv_k<16, 32, 128><<<(BATCH*32*64*64   + T-1)/T, T>>>((const float*)p_a1, w2, b2, (float*)p_a2);
    inorm_k<<<BATCH*32,  T>>>((float*)p_a2, g2, be2, 32, 64*64);
    conv_k<32, 64, 64 ><<<(BATCH*64*32*32   + T-1)/T, T>>>((const float*)p_a2, w3, b3, (float*)p_a3);
    inorm_k<<<BATCH*64,  T>>>((float*)p_a3, g3, be3, 64, 32*32);
    conv_k<64, 128, 32><<<(BATCH*128*16*16  + T-1)/T, T>>>((const float*)p_a3, w4, b4, (float*)p_a4);
    inorm_k<<<BATCH*128, T>>>((float*)p_a4, g4, be4, 128, 16*16);
    conv_k<128,128, 16><<<(BATCH*128*8*8    + T-1)/T, T>>>((const float*)p_a4, w5, b5, (float*)p_a5);

    fc_k<<<BATCH, 512>>>(wgen_w, wgen_b, ada_w, ada_b);
    lut_k<<<(BATCH*V3 + T-1)/T, T>>>(basis_w);

    trans_k<<<(BATCH*(NPIX/4) + T-1)/T, T>>>(imgs, out);
}

// round 3
// speedup vs baseline: 1.2191x; 1.1468x over previous
#include <cuda_runtime.h>
#include <cuda_fp16.h>
#include <math.h>

#define V 33
#define V3 (V*V*V)          // 35937
#define BATCH 2
#define HW 2048
#define NPIX (HW*HW)

// ---------------- scratch (static device globals; no allocation) -------------
__device__ float  g_rs[BATCH*3*256*256];
__device__ float  g_a1[BATCH*16*128*128];
__device__ float  g_a2[BATCH*32*64*64];
__device__ float  g_a3[BATCH*64*32*32];
__device__ float  g_a4[BATCH*128*16*16];
__device__ float  g_a5[BATCH*128*8*8];
__device__ float  g_wts[BATCH*3];
__device__ float  g_vert[BATCH*3*V];
__device__ float4 g_tbl[BATCH*3*256];   // inverse lookup table {idx, v0, v1, inv}

// fp16 pair-packed LUT: entry i holds {r,g,b} of cells i and i+1 (16B aligned)
struct alignas(16) LutPair { __half2 rr, gg, bb, pad; };
__device__ LutPair g_lut16[BATCH*V3];

// ---------------- stage 1: bilinear 2048 -> 256 (scale exactly 8) ------------
__global__ void resize_k(const float* __restrict__ img) {
    int i = blockIdx.x * blockDim.x + threadIdx.x;
    if (i >= BATCH*3*256*256) return;
    int ox = i & 255;
    int oy = (i >> 8) & 255;
    int pc = i >> 16;                       // b*3 + c
    const float* p = img + (size_t)pc * NPIX;
    int iy = oy*8 + 3, ix = ox*8 + 3;
    float p00 = p[(size_t)iy*HW + ix];
    float p01 = p[(size_t)iy*HW + ix + 1];
    float p10 = p[(size_t)(iy+1)*HW + ix];
    float p11 = p[(size_t)(iy+1)*HW + ix + 1];
    float r0 = 0.5f*p00 + 0.5f*p10;
    float r1 = 0.5f*p01 + 0.5f*p11;
    g_rs[i] = 0.5f*r0 + 0.5f*r1;
}

// ------- direct conv 3x3 stride 2 pad 1 + bias + lrelu, weights in smem ------
// One (b, co) per block-group; all threads in a block share co -> smem weights
// are pure broadcast. bpp = plane/TPB blocks per (b,co) plane.
template<int CI, int CO, int HIN, int TPB>
__global__ __launch_bounds__(TPB) void conv_k(const float* __restrict__ in,
                       const float* __restrict__ w,
                       const float* __restrict__ bias, float* __restrict__ out) {
    const int HO = HIN / 2;
    const int PLANE = HO * HO;
    const int BPP = PLANE / TPB;            // blocks per plane (exact for our sizes)
    int blk  = blockIdx.x;
    int pix  = (blk % BPP) * TPB + threadIdx.x;
    int co   = (blk / BPP) % CO;
    int b    = blk / (BPP * CO);

    __shared__ float sw[CI*9];
    for (int i = threadIdx.x; i < CI*9; i += TPB) sw[i] = w[(size_t)co*CI*9 + i];
    __syncthreads();

    int ox = pix % HO;
    int oy = pix / HO;
    float acc = bias[co];
    const float* ib = in + (size_t)b*CI*HIN*HIN;
    int iy0 = oy*2 - 1, ix0 = ox*2 - 1;
    if (iy0 >= 0 && ix0 >= 0) {
        const float* ip = ib + (size_t)iy0*HIN + ix0;
        const float* wp = sw;
        for (int ci = 0; ci < CI; ci++) {
            acc += ip[0]      *wp[0] + ip[1]      *wp[1] + ip[2]      *wp[2];
            acc += ip[HIN]    *wp[3] + ip[HIN+1]  *wp[4] + ip[HIN+2]  *wp[5];
            acc += ip[2*HIN]  *wp[6] + ip[2*HIN+1]*wp[7] + ip[2*HIN+2]*wp[8];
            ip += HIN*HIN;
            wp += 9;
        }
    } else {
        for (int ci = 0; ci < CI; ci++) {
            const float* ip = ib + (size_t)ci*HIN*HIN;
            const float* wp = sw + ci*9;
            #pragma unroll
            for (int ky = 0; ky < 3; ky++) {
                int iy = iy0 + ky;
                if ((unsigned)iy >= (unsigned)HIN) continue;
                #pragma unroll
                for (int kx = 0; kx < 3; kx++) {
                    int ix = ix0 + kx;
                    if ((unsigned)ix >= (unsigned)HIN) continue;
                    acc += ip[iy*HIN + ix] * wp[ky*3 + kx];
                }
            }
        }
    }
    out[(size_t)(b*CO + co)*PLANE + pix] = acc >= 0.f ? acc : 0.2f*acc;
}

// ---------------- instance norm, in place (block per (b,c)) ------------------
__global__ void inorm_k(float* __restrict__ x, const float* __restrict__ g,
                        const float* __restrict__ be, int C, int N) {
    int bc = blockIdx.x;
    int c  = bc % C;
    float* p = x + (size_t)bc * N;
    float s = 0.f, s2 = 0.f;
    for (int i = threadIdx.x; i < N; i += blockDim.x) { float v = p[i]; s += v; s2 += v*v; }
    __shared__ float sa[256], sb[256];
    sa[threadIdx.x] = s; sb[threadIdx.x] = s2;
    __syncthreads();
    for (int o = 128; o > 0; o >>= 1) {
        if (threadIdx.x < o) { sa[threadIdx.x] += sa[threadIdx.x+o]; sb[threadIdx.x] += sb[threadIdx.x+o]; }
        __syncthreads();
    }
    __shared__ float s_a, s_b;
    if (threadIdx.x == 0) {
        float m   = sa[0] / (float)N;
        float var = sb[0] / (float)N - m*m;
        float inv = rsqrtf(var + 1e-5f);
        float a   = inv * g[c];
        s_a = a;
        s_b = be[c] - m * a;
    }
    __syncthreads();
    float a = s_a, bt = s_b;
    for (int i = threadIdx.x; i < N; i += blockDim.x) p[i] = p[i]*a + bt;
}

// ---------------- pool 8x8 -> (2,2), FCs, softmax+cumsum ---------------------
__global__ void fc_k(const float* __restrict__ wgen_w, const float* __restrict__ wgen_b,
                     const float* __restrict__ ada_w,  const float* __restrict__ ada_b) {
    int b = blockIdx.x;
    int t = threadIdx.x;
    __shared__ float sx[512];
    __shared__ float slog[96];
    {
        int c  = t >> 2;
        int ij = t & 3;
        int i0 = (ij >> 1) * 4;
        int j0 = (ij & 1) * 4;
        const float* p = g_a5 + (size_t)(b*128 + c) * 64;
        float s = 0.f;
        #pragma unroll
        for (int pp = 0; pp < 4; pp++)
            #pragma unroll
            for (int qq = 0; qq < 4; qq++)
                s += p[(i0+pp)*8 + j0+qq];
        sx[t] = s * (1.f/16.f);
    }
    __syncthreads();
    if (t < 96) {
        float d = ada_b[t];
        for (int m = 0; m < 512; m++) d += sx[m] * ada_w[m*96 + t];
        slog[t] = d;
    } else if (t < 99) {
        int n = t - 96;
        float d = wgen_b[n];
        for (int m = 0; m < 512; m++) d += sx[m] * wgen_w[m*3 + n];
        g_wts[b*3 + n] = d;
    }
    __syncthreads();
    if (t < 3) {
        float mx = -1e30f;
        for (int k = 0; k < 32; k++) mx = fmaxf(mx, slog[t*32 + k]);
        float e[32]; float sum = 0.f;
        for (int k = 0; k < 32; k++) { e[k] = expf(slog[t*32 + k] - mx); sum += e[k]; }
        float isum = 1.f / sum;
        float* vp = g_vert + (b*3 + t) * V;
        vp[0] = 0.f;
        float run = 0.f;
        for (int k = 0; k < 32; k++) { run += e[k]*isum; vp[k+1] = run; }
    }
}

// -------- inverse-table build: 256 bins per (b,c), {idx, v0, v1, inv} --------
__global__ void tbl_k() {
    int bc = blockIdx.x;              // 0..BATCH*3-1
    int k  = threadIdx.x;             // 0..255
    const float* v = g_vert + bc*V;
    float q = (float)k * (1.f/256.f); // bin start
    int pos = 0;
    #pragma unroll
    for (int s = 16; s >= 1; s >>= 1)
        if (v[pos + s] <= q) pos += s;
    float v0 = v[pos], v1 = v[pos+1];
    float4 e;
    e.x = (float)pos;
    e.y = v0;
    e.z = v1;
    e.w = 1.f / fmaxf(v1 - v0, 1e-10f);
    g_tbl[bc*256 + k] = e;
}

// ---------------- build fp16 pair-packed LUT ---------------------------------
__global__ void lut_k(const float* __restrict__ basis_w) {
    int i = blockIdx.x * blockDim.x + threadIdx.x;
    if (i >= BATCH*V3) return;
    int b    = i / V3;
    int flat = i % V3;
    int flat2 = flat + 1 < V3 ? flat + 1 : V3 - 1;
    float w0 = g_wts[b*3+0], w1 = g_wts[b*3+1], w2 = g_wts[b*3+2];
    float r0 = w0*basis_w[0*3*V3 + 0*V3 + flat]  + w1*basis_w[1*3*V3 + 0*V3 + flat]  + w2*basis_w[2*3*V3 + 0*V3 + flat];
    float g0 = w0*basis_w[0*3*V3 + 1*V3 + flat]  + w1*basis_w[1*3*V3 + 1*V3 + flat]  + w2*basis_w[2*3*V3 + 1*V3 + flat];
    float b0 = w0*basis_w[0*3*V3 + 2*V3 + flat]  + w1*basis_w[1*3*V3 + 2*V3 + flat]  + w2*basis_w[2*3*V3 + 2*V3 + flat];
    float r1 = w0*basis_w[0*3*V3 + 0*V3 + flat2] + w1*basis_w[1*3*V3 + 0*V3 + flat2] + w2*basis_w[2*3*V3 + 0*V3 + flat2];
    float g1 = w0*basis_w[0*3*V3 + 1*V3 + flat2] + w1*basis_w[1*3*V3 + 1*V3 + flat2] + w2*basis_w[2*3*V3 + 1*V3 + flat2];
    float b1 = w0*basis_w[0*3*V3 + 2*V3 + flat2] + w1*basis_w[1*3*V3 + 2*V3 + flat2] + w2*basis_w[2*3*V3 + 2*V3 + flat2];
    LutPair o;
    o.rr = __floats2half2_rn(r0, r1);
    o.gg = __floats2half2_rn(g0, g1);
    o.bb = __floats2half2_rn(b0, b1);
    o.pad = __floats2half2_rn(0.f, 0.f);
    g_lut16[i] = o;
}

// ---------------- trilinear LUT transform ------------------------------------
__device__ __forceinline__ void lut_lookup(const float4* __restrict__ tbl,
                                           const float* __restrict__ v, float q,
                                           int& idx, float& f) {
    q = fminf(fmaxf(q, 0.f), 1.f);
    int k = min(255, (int)(q * 256.f));
    float4 e = tbl[k];
    int   i  = (int)e.x;
    float v0 = e.y, v1 = e.z, inv = e.w;
    // at most 1 correction in practice (intervals ~1/32 >> bin 1/256); loop bounded for safety
    while (v1 <= q && i < 31) {
        i++; v0 = v1; v1 = v[i+1];
        inv = 1.f / fmaxf(v1 - v0, 1e-10f);
    }
    idx = i;
    f = fminf((q - v0) * inv, 1.f);
}

__device__ __forceinline__ float3 apply_px(float r, float g, float bl,
        const float4* __restrict__ tr, const float4* __restrict__ tg,
        const float4* __restrict__ tb,
        const float* __restrict__ vr, const float* __restrict__ vg,
        const float* __restrict__ vb, const float4* __restrict__ lb) {
    int ir, ig, ib;
    float fr, fg, fb;
    lut_lookup(tr, vr, r,  ir, fr);
    lut_lookup(tg, vg, g,  ig, fg);
    lut_lookup(tb, vb, bl, ib, fb);
    int base = (ib*V + ig)*V + ir;
    float3 acc = make_float3(0.f, 0.f, 0.f);
    float omfr = 1.f - fr;
    #pragma unroll
    for (int db = 0; db < 2; db++) {
        float wb_ = db ? fb : 1.f - fb;
        #pragma unroll
        for (int dg = 0; dg < 2; dg++) {
            float wg_ = wb_ * (dg ? fg : 1.f - fg);
            int off = base + db*V*V + dg*V;
            float4 raw = __ldg(lb + off);
            float2 rv = __half22float2(*reinterpret_cast<const __half2*>(&raw.x));
            float2 gv = __half22float2(*reinterpret_cast<const __half2*>(&raw.y));
            float2 bv = __half22float2(*reinterpret_cast<const __half2*>(&raw.z));
            float w0 = wg_ * omfr;
            float w1 = wg_ * fr;
            acc.x += w0*rv.x + w1*rv.y;
            acc.y += w0*gv.x + w1*gv.y;
            acc.z += w0*bv.x + w1*bv.y;
        }
    }
    return acc;
}

__global__ __launch_bounds__(256) void trans_k(const float* __restrict__ img,
                                               float* __restrict__ out) {
    __shared__ float4 stbl[3*256];
    __shared__ float  sv[3*V];
    const int PPT = 8;                                   // pixels per thread
    const int BPB = (NPIX/PPT) / 256;                    // blocks per batch = 2048
    int b   = blockIdx.x / BPB;
    int blk = blockIdx.x % BPB;

    for (int i = threadIdx.x; i < 3*256; i += 256) stbl[i] = g_tbl[b*3*256 + i];
    for (int i = threadIdx.x; i < 3*V;   i += 256) sv[i]   = g_vert[b*3*V + i];
    __syncthreads();

    int q8 = blk*256 + threadIdx.x;                      // chunk of 8 pixels
    int q  = q8 * 2;                                     // float4 index (2 per chunk)

    const float4* rp = (const float4*)(img + (size_t)(b*3+0)*NPIX);
    const float4* gp = (const float4*)(img + (size_t)(b*3+1)*NPIX);
    const float4* bp = (const float4*)(img + (size_t)(b*3+2)*NPIX);
    const float4* tr = stbl;
    const float4* tg = stbl + 256;
    const float4* tb = stbl + 512;
    const float*  vr = sv;
    const float*  vg = sv + V;
    const float*  vb = sv + 2*V;
    const float4* lb = reinterpret_cast<const float4*>(g_lut16) + (size_t)b*V3;

    float4* orp = (float4*)(out + (size_t)(b*3+0)*NPIX);
    float4* ogp = (float4*)(out + (size_t)(b*3+1)*NPIX);
    float4* obp = (float4*)(out + (size_t)(b*3+2)*NPIX);

    #pragma unroll
    for (int h = 0; h < 2; h++) {
        float4 R = rp[q+h], G = gp[q+h], Bl = bp[q+h];
        float3 o0 = apply_px(R.x, G.x, Bl.x, tr, tg, tb, vr, vg, vb, lb);
        float3 o1 = apply_px(R.y, G.y, Bl.y, tr, tg, tb, vr, vg, vb, lb);
        float3 o2 = apply_px(R.z, G.z, Bl.z, tr, tg, tb, vr, vg, vb, lb);
        float3 o3 = apply_px(R.w, G.w, Bl.w, tr, tg, tb, vr, vg, vb, lb);
        orp[q+h] = make_float4(o0.x, o1.x, o2.x, o3.x);
        ogp[q+h] = make_float4(o0.y, o1.y, o2.y, o3.y);
        obp[q+h] = make_float4(o0.z, o1.z, o2.z, o3.z);
    }
}

// ---------------- launch ------------------------------------------------------
extern "C" void kernel_launch(void* const* d_in, const int* in_sizes, int n_in,
                              void* d_out, int out_size) {
    const float* imgs   = (const float*)d_in[0];
    const float* w1 = (const float*)d_in[1];  const float* b1 = (const float*)d_in[2];
    const float* g1 = (const float*)d_in[3];  const float* be1 = (const float*)d_in[4];
    const float* w2 = (const float*)d_in[5];  const float* b2 = (const float*)d_in[6];
    const float* g2 = (const float*)d_in[7];  const float* be2 = (const float*)d_in[8];
    const float* w3 = (const float*)d_in[9];  const float* b3 = (const float*)d_in[10];
    const float* g3 = (const float*)d_in[11]; const float* be3 = (const float*)d_in[12];
    const float* w4 = (const float*)d_in[13]; const float* b4 = (const float*)d_in[14];
    const float* g4 = (const float*)d_in[15]; const float* be4 = (const float*)d_in[16];
    const float* w5 = (const float*)d_in[17]; const float* b5 = (const float*)d_in[18];
    const float* wgen_w = (const float*)d_in[19]; const float* wgen_b = (const float*)d_in[20];
    const float* basis_w = (const float*)d_in[21];
    const float* ada_w = (const float*)d_in[22]; const float* ada_b = (const float*)d_in[23];
    float* out = (float*)d_out;

    void *p_rs, *p_a1, *p_a2, *p_a3, *p_a4, *p_a5;
    cudaGetSymbolAddress(&p_rs, g_rs);
    cudaGetSymbolAddress(&p_a1, g_a1);
    cudaGetSymbolAddress(&p_a2, g_a2);
    cudaGetSymbolAddress(&p_a3, g_a3);
    cudaGetSymbolAddress(&p_a4, g_a4);
    cudaGetSymbolAddress(&p_a5, g_a5);

    const int T = 256;

    resize_k<<<(BATCH*3*256*256 + T-1)/T, T>>>(imgs);

    // conv grids: B * CO * (plane/TPB)
    conv_k<3,  16, 256, 256><<<BATCH*16*(128*128/256), 256>>>((const float*)p_rs, w1, b1, (float*)p_a1);
    inorm_k<<<BATCH*16,  T>>>((float*)p_a1, g1, be1, 16, 128*128);
    conv_k<16, 32, 128, 256><<<BATCH*32*(64*64/256),   256>>>((const float*)p_a1, w2, b2, (float*)p_a2);
    inorm_k<<<BATCH*32,  T>>>((float*)p_a2, g2, be2, 32, 64*64);
    conv_k<32, 64, 64, 256><<<BATCH*64*(32*32/256),    256>>>((const float*)p_a2, w3, b3, (float*)p_a3);
    inorm_k<<<BATCH*64,  T>>>((float*)p_a3, g3, be3, 64, 32*32);
    conv_k<64, 128, 32, 256><<<BATCH*128*(16*16/256),  256>>>((const float*)p_a3, w4, b4, (float*)p_a4);
    inorm_k<<<BATCH*128, T>>>((float*)p_a4, g4, be4, 128, 16*16);
    conv_k<128,128, 16, 64><<<BATCH*128*(8*8/64),      64>>>((const float*)p_a4, w5, b5, (float*)p_a5);

    fc_k<<<BATCH, 512>>>(wgen_w, wgen_b, ada_w, ada_b);
    tbl_k<<<BATCH*3, 256>>>();
    lut_k<<<(BATCH*V3 + T-1)/T, T>>>(basis_w);

    trans_k<<<BATCH*((NPIX/8)/256), 256>>>(imgs, out);
}

// round 5
// speedup vs baseline: 1.2576x; 1.0316x over previous
#include <cuda_runtime.h>
#include <cuda_fp16.h>
#include <cstdint>
#include <math.h>

#define V 33
#define V3 (V*V*V)          // 35937
#define BATCH 2
#define HW 2048
#define NPIX (HW*HW)

// ---------------- scratch (static device globals; no allocation) -------------
__device__ float  g_rs[BATCH*3*256*256];
__device__ float  g_a1[BATCH*16*128*128];
__device__ float  g_a2[BATCH*32*64*64];
__device__ float  g_a3[BATCH*64*32*32];
__device__ float  g_a4[BATCH*128*16*16];
__device__ float  g_a5[BATCH*128*8*8];
__device__ float  g_wts[BATCH*3];
__device__ float  g_vert[BATCH*3*V];
__device__ float4 g_tbl[BATCH*3*256];   // inverse lookup table {idx, v0, v1, inv}

// quad-packed fp16 LUT: entry(flat=(ib,ig,ir)) holds the 4 (dg,dr) corners
// of the (ig,ir) cell at blue-plane ib. 32B aligned -> 1 sector per entry.
struct alignas(32) Lut4 { uint4 rg; uint2 bb; uint2 pad; };
__device__ Lut4 g_lut4[BATCH*V3];

__device__ __forceinline__ unsigned int h2u(__half2 h) {
    return *reinterpret_cast<unsigned int*>(&h);
}

// ---------------- stage 1: bilinear 2048 -> 256 (scale exactly 8) ------------
__global__ void resize_k(const float* __restrict__ img) {
    int i = blockIdx.x * blockDim.x + threadIdx.x;
    if (i >= BATCH*3*256*256) return;
    int ox = i & 255;
    int oy = (i >> 8) & 255;
    int pc = i >> 16;                       // b*3 + c
    const float* p = img + (size_t)pc * NPIX;
    int iy = oy*8 + 3, ix = ox*8 + 3;
    float p00 = p[(size_t)iy*HW + ix];
    float p01 = p[(size_t)iy*HW + ix + 1];
    float p10 = p[(size_t)(iy+1)*HW + ix];
    float p11 = p[(size_t)(iy+1)*HW + ix + 1];
    float r0 = 0.5f*p00 + 0.5f*p10;
    float r1 = 0.5f*p01 + 0.5f*p11;
    g_rs[i] = 0.5f*r0 + 0.5f*r1;
}

// ------- direct conv 3x3 stride 2 pad 1 + bias + lrelu, weights in smem ------
template<int CI, int CO, int HIN, int TPB>
__global__ __launch_bounds__(TPB) void conv_k(const float* __restrict__ in,
                       const float* __restrict__ w,
                       const float* __restrict__ bias, float* __restrict__ out) {
    const int HO = HIN / 2;
    const int PLANE = HO * HO;
    const int BPP = PLANE / TPB;            // blocks per plane (exact for our sizes)
    int blk  = blockIdx.x;
    int pix  = (blk % BPP) * TPB + threadIdx.x;
    int co   = (blk / BPP) % CO;
    int b    = blk / (BPP * CO);

    __shared__ float sw[CI*9];
    for (int i = threadIdx.x; i < CI*9; i += TPB) sw[i] = w[(size_t)co*CI*9 + i];
    __syncthreads();

    int ox = pix % HO;
    int oy = pix / HO;
    float acc = bias[co];
    const float* ib = in + (size_t)b*CI*HIN*HIN;
    int iy0 = oy*2 - 1, ix0 = ox*2 - 1;
    if (iy0 >= 0 && ix0 >= 0) {
        const float* ip = ib + (size_t)iy0*HIN + ix0;
        const float* wp = sw;
        for (int ci = 0; ci < CI; ci++) {
            acc += ip[0]      *wp[0] + ip[1]      *wp[1] + ip[2]      *wp[2];
            acc += ip[HIN]    *wp[3] + ip[HIN+1]  *wp[4] + ip[HIN+2]  *wp[5];
            acc += ip[2*HIN]  *wp[6] + ip[2*HIN+1]*wp[7] + ip[2*HIN+2]*wp[8];
            ip += HIN*HIN;
            wp += 9;
        }
    } else {
        for (int ci = 0; ci < CI; ci++) {
            const float* ip = ib + (size_t)ci*HIN*HIN;
            const float* wp = sw + ci*9;
            #pragma unroll
            for (int ky = 0; ky < 3; ky++) {
                int iy = iy0 + ky;
                if ((unsigned)iy >= (unsigned)HIN) continue;
                #pragma unroll
                for (int kx = 0; kx < 3; kx++) {
                    int ix = ix0 + kx;
                    if ((unsigned)ix >= (unsigned)HIN) continue;
                    acc += ip[iy*HIN + ix] * wp[ky*3 + kx];
                }
            }
        }
    }
    out[(size_t)(b*CO + co)*PLANE + pix] = acc >= 0.f ? acc : 0.2f*acc;
}

// ---------------- instance norm, in place (block per (b,c)) ------------------
__global__ void inorm_k(float* __restrict__ x, const float* __restrict__ g,
                        const float* __restrict__ be, int C, int N) {
    int bc = blockIdx.x;
    int c  = bc % C;
    float* p = x + (size_t)bc * N;
    float s = 0.f, s2 = 0.f;
    for (int i = threadIdx.x; i < N; i += blockDim.x) { float v = p[i]; s += v; s2 += v*v; }
    __shared__ float sa[256], sb[256];
    sa[threadIdx.x] = s; sb[threadIdx.x] = s2;
    __syncthreads();
    for (int o = 128; o > 0; o >>= 1) {
        if (threadIdx.x < o) { sa[threadIdx.x] += sa[threadIdx.x+o]; sb[threadIdx.x] += sb[threadIdx.x+o]; }
        __syncthreads();
    }
    __shared__ float s_a, s_b;
    if (threadIdx.x == 0) {
        float m   = sa[0] / (float)N;
        float var = sb[0] / (float)N - m*m;
        float inv = rsqrtf(var + 1e-5f);
        float a   = inv * g[c];
        s_a = a;
        s_b = be[c] - m * a;
    }
    __syncthreads();
    float a = s_a, bt = s_b;
    for (int i = threadIdx.x; i < N; i += blockDim.x) p[i] = p[i]*a + bt;
}

// ---------------- pool 8x8 -> (2,2), FCs, softmax+cumsum ---------------------
__global__ void fc_k(const float* __restrict__ wgen_w, const float* __restrict__ wgen_b,
                     const float* __restrict__ ada_w,  const float* __restrict__ ada_b) {
    int b = blockIdx.x;
    int t = threadIdx.x;
    __shared__ float sx[512];
    __shared__ float slog[96];
    {
        int c  = t >> 2;
        int ij = t & 3;
        int i0 = (ij >> 1) * 4;
        int j0 = (ij & 1) * 4;
        const float* p = g_a5 + (size_t)(b*128 + c) * 64;
        float s = 0.f;
        #pragma unroll
        for (int pp = 0; pp < 4; pp++)
            #pragma unroll
            for (int qq = 0; qq < 4; qq++)
                s += p[(i0+pp)*8 + j0+qq];
        sx[t] = s * (1.f/16.f);
    }
    __syncthreads();
    if (t < 96) {
        float d = ada_b[t];
        for (int m = 0; m < 512; m++) d += sx[m] * ada_w[m*96 + t];
        slog[t] = d;
    } else if (t < 99) {
        int n = t - 96;
        float d = wgen_b[n];
        for (int m = 0; m < 512; m++) d += sx[m] * wgen_w[m*3 + n];
        g_wts[b*3 + n] = d;
    }
    __syncthreads();
    if (t < 3) {
        float mx = -1e30f;
        for (int k = 0; k < 32; k++) mx = fmaxf(mx, slog[t*32 + k]);
        float e[32]; float sum = 0.f;
        for (int k = 0; k < 32; k++) { e[k] = expf(slog[t*32 + k] - mx); sum += e[k]; }
        float isum = 1.f / sum;
        float* vp = g_vert + (b*3 + t) * V;
        vp[0] = 0.f;
        float run = 0.f;
        for (int k = 0; k < 32; k++) { run += e[k]*isum; vp[k+1] = run; }
    }
}

// -------- inverse-table build: 256 bins per (b,c), {idx, v0, v1, inv} --------
__global__ void tbl_k() {
    int bc = blockIdx.x;              // 0..BATCH*3-1
    int k  = threadIdx.x;             // 0..255
    const float* v = g_vert + bc*V;
    float q = (float)k * (1.f/256.f); // bin start
    int pos = 0;
    #pragma unroll
    for (int s = 16; s >= 1; s >>= 1)
        if (v[pos + s] <= q) pos += s;
    float v0 = v[pos], v1 = v[pos+1];
    float4 e;
    e.x = (float)pos;
    e.y = v0;
    e.z = v1;
    e.w = 1.f / fmaxf(v1 - v0, 1e-10f);
    g_tbl[bc*256 + k] = e;
}

// ---------------- build quad-packed fp16 LUT ---------------------------------
__global__ void lut_k(const float* __restrict__ basis_w) {
    int i = blockIdx.x * blockDim.x + threadIdx.x;
    if (i >= BATCH*V3) return;
    int b    = i / V3;
    int flat = i % V3;
    int ir   = flat % V;
    int ig   = (flat / V) % V;
    int dro  = (ir < V-1) ? 1 : 0;
    int dgo  = (ig < V-1) ? V : 0;
    int f00 = flat, f01 = flat + dro, f10 = flat + dgo, f11 = flat + dgo + dro;
    float w0 = g_wts[b*3+0], w1 = g_wts[b*3+1], w2 = g_wts[b*3+2];
    const float* bw = basis_w;
    #define LVAL(ch, f) (w0*bw[0*3*V3 + (ch)*V3 + (f)] + w1*bw[1*3*V3 + (ch)*V3 + (f)] + w2*bw[2*3*V3 + (ch)*V3 + (f)])
    __half2 r01 = __floats2half2_rn(LVAL(0, f00), LVAL(0, f01));
    __half2 r23 = __floats2half2_rn(LVAL(0, f10), LVAL(0, f11));
    __half2 g01 = __floats2half2_rn(LVAL(1, f00), LVAL(1, f01));
    __half2 g23 = __floats2half2_rn(LVAL(1, f10), LVAL(1, f11));
    __half2 b01 = __floats2half2_rn(LVAL(2, f00), LVAL(2, f01));
    __half2 b23 = __floats2half2_rn(LVAL(2, f10), LVAL(2, f11));
    #undef LVAL
    Lut4 o;
    o.rg = make_uint4(h2u(r01), h2u(r23), h2u(g01), h2u(g23));
    o.bb = make_uint2(h2u(b01), h2u(b23));
    o.pad = make_uint2(0u, 0u);
    g_lut4[i] = o;
}

// ---------------- trilinear LUT transform ------------------------------------
__device__ __forceinline__ void lut_lookup(const float4* __restrict__ tbl,
                                           const float* __restrict__ v, float q,
                                           int& idx, float& f) {
    q = fminf(fmaxf(q, 0.f), 1.f);
    int k = min(255, (int)(q * 256.f));
    float4 e = tbl[k];
    int   i  = (int)e.x;
    float v0 = e.y, v1 = e.z, inv = e.w;
    while (v1 <= q && i < 31) {
        i++; v0 = v1; v1 = v[i+1];
        inv = 1.f / fmaxf(v1 - v0, 1e-10f);
    }
    idx = i;
    f = fminf((q - v0) * inv, 1.f);
}

__device__ __forceinline__ float3 interp4(const Lut4* __restrict__ e,
        float w00, float w01, float w10, float w11) {
    uint4 rg = __ldg(&e->rg);
    uint2 bb = __ldg(&e->bb);
    float2 r01 = __half22float2(*reinterpret_cast<const __half2*>(&rg.x));
    float2 r23 = __half22float2(*reinterpret_cast<const __half2*>(&rg.y));
    float2 g01 = __half22float2(*reinterpret_cast<const __half2*>(&rg.z));
    float2 g23 = __half22float2(*reinterpret_cast<const __half2*>(&rg.w));
    float2 b01 = __half22float2(*reinterpret_cast<const __half2*>(&bb.x));
    float2 b23 = __half22float2(*reinterpret_cast<const __half2*>(&bb.y));
    float3 o;
    o.x = w00*r01.x + w01*r01.y + w10*r23.x + w11*r23.y;
    o.y = w00*g01.x + w01*g01.y + w10*g23.x + w11*g23.y;
    o.z = w00*b01.x + w01*b01.y + w10*b23.x + w11*b23.y;
    return o;
}

__device__ __forceinline__ float3 apply_px(float r, float g, float bl,
        const float4* __restrict__ tr, const float4* __restrict__ tg,
        const float4* __restrict__ tb,
        const float* __restrict__ vr, const float* __restrict__ vg,
        const float* __restrict__ vb, const Lut4* __restrict__ lb) {
    int ir, ig, ib;
    float fr, fg, fb;
    lut_lookup(tr, vr, r,  ir, fr);
    lut_lookup(tg, vg, g,  ig, fg);
    lut_lookup(tb, vb, bl, ib, fb);
    int base = (ib*V + ig)*V + ir;
    float w00 = (1.f-fg)*(1.f-fr);
    float w01 = (1.f-fg)*fr;
    float w10 = fg*(1.f-fr);
    float w11 = fg*fr;
    float3 lo = interp4(lb + base,       w00, w01, w10, w11);
    float3 hi = interp4(lb + base + V*V, w00, w01, w10, w11);
    float omfb = 1.f - fb;
    return make_float3(omfb*lo.x + fb*hi.x,
                       omfb*lo.y + fb*hi.y,
                       omfb*lo.z + fb*hi.z);
}

__global__ __launch_bounds__(256) void trans_k(const float* __restrict__ img,
                                               float* __restrict__ out) {
    __shared__ float4 stbl[3*256];
    __shared__ float  sv[3*V];
    const int PPT = 8;                                   // pixels per thread
    const int BPB = (NPIX/PPT) / 256;                    // blocks per batch = 2048
    int b   = blockIdx.x / BPB;
    int blk = blockIdx.x % BPB;

    for (int i = threadIdx.x; i < 3*256; i += 256) stbl[i] = g_tbl[b*3*256 + i];
    for (int i = threadIdx.x; i < 3*V;   i += 256) sv[i]   = g_vert[b*3*V + i];
    __syncthreads();

    int q8 = blk*256 + threadIdx.x;                      // chunk of 8 pixels
    int q  = q8 * 2;                                     // float4 index (2 per chunk)

    const float4* rp = (const float4*)(img + (size_t)(b*3+0)*NPIX);
    const float4* gp = (const float4*)(img + (size_t)(b*3+1)*NPIX);
    const float4* bp = (const float4*)(img + (size_t)(b*3+2)*NPIX);
    const float4* tr = stbl;
    const float4* tg = stbl + 256;
    const float4* tb = stbl + 512;
    const float*  vr = sv;
    const float*  vg = sv + V;
    const float*  vb = sv + 2*V;
    const Lut4*   lb = g_lut4 + (size_t)b*V3;

    float4* orp = (float4*)(out + (size_t)(b*3+0)*NPIX);
    float4* ogp = (float4*)(out + (size_t)(b*3+1)*NPIX);
    float4* obp = (float4*)(out + (size_t)(b*3+2)*NPIX);

    #pragma unroll
    for (int h = 0; h < 2; h++) {
        float4 R = rp[q+h], G = gp[q+h], Bl = bp[q+h];
        float3 o0 = apply_px(R.x, G.x, Bl.x, tr, tg, tb, vr, vg, vb, lb);
        float3 o1 = apply_px(R.y, G.y, Bl.y, tr, tg, tb, vr, vg, vb, lb);
        float3 o2 = apply_px(R.z, G.z, Bl.z, tr, tg, tb, vr, vg, vb, lb);
        float3 o3 = apply_px(R.w, G.w, Bl.w, tr, tg, tb, vr, vg, vb, lb);
        orp[q+h] = make_float4(o0.x, o1.x, o2.x, o3.x);
        ogp[q+h] = make_float4(o0.y, o1.y, o2.y, o3.y);
        obp[q+h] = make_float4(o0.z, o1.z, o2.z, o3.z);
    }
}

// ---------------- launch ------------------------------------------------------
extern "C" void kernel_launch(void* const* d_in, const int* in_sizes, int n_in,
                              void* d_out, int out_size) {
    const float* imgs   = (const float*)d_in[0];
    const float* w1 = (const float*)d_in[1];  const float* b1 = (const float*)d_in[2];
    const float* g1 = (const float*)d_in[3];  const float* be1 = (const float*)d_in[4];
    const float* w2 = (const float*)d_in[5];  const float* b2 = (const float*)d_in[6];
    const float* g2 = (const float*)d_in[7];  const float* be2 = (const float*)d_in[8];
    const float* w3 = (const float*)d_in[9];  const float* b3 = (const float*)d_in[10];
    const float* g3 = (const float*)d_in[11]; const float* be3 = (const float*)d_in[12];
    const float* w4 = (const float*)d_in[13]; const float* b4 = (const float*)d_in[14];
    const float* g4 = (const float*)d_in[15]; const float* be4 = (const float*)d_in[16];
    const float* w5 = (const float*)d_in[17]; const float* b5 = (const float*)d_in[18];
    const float* wgen_w = (const float*)d_in[19]; const float* wgen_b = (const float*)d_in[20];
    const float* basis_w = (const float*)d_in[21];
    const float* ada_w = (const float*)d_in[22]; const float* ada_b = (const float*)d_in[23];
    float* out = (float*)d_out;

    void *p_rs, *p_a1, *p_a2, *p_a3, *p_a4, *p_a5;
    cudaGetSymbolAddress(&p_rs, g_rs);
    cudaGetSymbolAddress(&p_a1, g_a1);
    cudaGetSymbolAddress(&p_a2, g_a2);
    cudaGetSymbolAddress(&p_a3, g_a3);
    cudaGetSymbolAddress(&p_a4, g_a4);
    cudaGetSymbolAddress(&p_a5, g_a5);

    const int T = 256;

    resize_k<<<(BATCH*3*256*256 + T-1)/T, T>>>(imgs);

    conv_k<3,  16, 256, 256><<<BATCH*16*(128*128/256), 256>>>((const float*)p_rs, w1, b1, (float*)p_a1);
    inorm_k<<<BATCH*16,  T>>>((float*)p_a1, g1, be1, 16, 128*128);
    conv_k<16, 32, 128, 256><<<BATCH*32*(64*64/256),   256>>>((const float*)p_a1, w2, b2, (float*)p_a2);
    inorm_k<<<BATCH*32,  T>>>((float*)p_a2, g2, be2, 32, 64*64);
    conv_k<32, 64, 64, 256><<<BATCH*64*(32*32/256),    256>>>((const float*)p_a2, w3, b3, (float*)p_a3);
    inorm_k<<<BATCH*64,  T>>>((float*)p_a3, g3, be3, 64, 32*32);
    conv_k<64, 128, 32, 256><<<BATCH*128*(16*16/256),  256>>>((const float*)p_a3, w4, b4, (float*)p_a4);
    inorm_k<<<BATCH*128, T>>>((float*)p_a4, g4, be4, 128, 16*16);
    conv_k<128,128, 16, 64><<<BATCH*128*(8*8/64),      64>>>((const float*)p_a4, w5, b5, (float*)p_a5);

    fc_k<<<BATCH, 512>>>(wgen_w, wgen_b, ada_w, ada_b);
    tbl_k<<<BATCH*3, 256>>>();
    lut_k<<<(BATCH*V3 + T-1)/T, T>>>(basis_w);

    trans_k<<<BATCH*((NPIX/8)/256), 256>>>(imgs, out);
}